// round 2
// baseline (speedup 1.0000x reference)
#include <cuda_runtime.h>
#include <cuda_bf16.h>

// FrozenBNBStableEmbedding: gather int8-coded embedding rows, dequant via
// 256-entry code table * per-block absmax, then LayerNorm with affine.
//
// NOTE: JAX default config disables x64, so the "int64" x tensor is actually
// int32 on device. Read it as const int*.
//
// Inputs (metadata order):
//   d_in[0] x         int32  [8,2048]        (16384 tokens)
//   d_in[1] weight_i8 int32  [50304,1024]    (values 0..255)
//   d_in[2] absmax    f32    [12576]
//   d_in[3] code      f32    [256]
//   d_in[4] ln_weight f32    [1024]
//   d_in[5] ln_bias   f32    [1024]
// Output: f32 [16384,1024]
//
// D=1024 divides BLOCK=4096 -> every row uses exactly one absmax scale:
// scale = absmax[row >> 2].

#define D 1024
#define TPB 256          // 4 elements per thread via int4/float4
#define EPS 1e-5f

__global__ __launch_bounds__(TPB) void emb_ln_kernel(
    const int*       __restrict__ x,
    const int*       __restrict__ w,
    const float*     __restrict__ absmax,
    const float*     __restrict__ code,
    const float*     __restrict__ lnw,
    const float*     __restrict__ lnb,
    float*           __restrict__ out)
{
    __shared__ float s_code[256];
    __shared__ float s_sum[8];
    __shared__ float s_sq[8];
    __shared__ float s_stats[2];

    const int tid  = threadIdx.x;
    const int warp = tid >> 5;
    const int lane = tid & 31;

    s_code[tid] = code[tid];

    const int row = x[blockIdx.x];       // uniform across CTA
    const float scale = __ldg(&absmax[row >> 2]);
    __syncthreads();

    // Load 4 consecutive int32 codes (16B) per thread
    const int4* wrow = reinterpret_cast<const int4*>(w + (long long)row * D);
    int4 q = __ldg(&wrow[tid]);

    float v0 = s_code[q.x & 255] * scale;
    float v1 = s_code[q.y & 255] * scale;
    float v2 = s_code[q.z & 255] * scale;
    float v3 = s_code[q.w & 255] * scale;

    // One-pass mean/var: sum and sum of squares
    float sum = v0 + v1 + v2 + v3;
    float sq  = v0*v0 + v1*v1 + v2*v2 + v3*v3;

    #pragma unroll
    for (int off = 16; off > 0; off >>= 1) {
        sum += __shfl_xor_sync(0xFFFFFFFFu, sum, off);
        sq  += __shfl_xor_sync(0xFFFFFFFFu, sq,  off);
    }
    if (lane == 0) { s_sum[warp] = sum; s_sq[warp] = sq; }
    __syncthreads();

    if (warp == 0) {
        float s = (lane < 8) ? s_sum[lane] : 0.0f;
        float z = (lane < 8) ? s_sq[lane]  : 0.0f;
        #pragma unroll
        for (int off = 4; off > 0; off >>= 1) {
            s += __shfl_xor_sync(0xFFFFFFFFu, s, off);
            z += __shfl_xor_sync(0xFFFFFFFFu, z, off);
        }
        if (lane == 0) {
            float mean = s * (1.0f / D);
            float var  = z * (1.0f / D) - mean * mean;
            s_stats[0] = mean;
            s_stats[1] = rsqrtf(var + EPS);
        }
    }
    __syncthreads();

    const float mean = s_stats[0];
    const float rstd = s_stats[1];

    const float4 gw = __ldg(&reinterpret_cast<const float4*>(lnw)[tid]);
    const float4 gb = __ldg(&reinterpret_cast<const float4*>(lnb)[tid]);

    float4 o;
    o.x = (v0 - mean) * rstd * gw.x + gb.x;
    o.y = (v1 - mean) * rstd * gw.y + gb.y;
    o.z = (v2 - mean) * rstd * gw.z + gb.z;
    o.w = (v3 - mean) * rstd * gw.w + gb.w;

    reinterpret_cast<float4*>(out)[blockIdx.x * (D / 4) + tid] = o;
}

extern "C" void kernel_launch(void* const* d_in, const int* in_sizes, int n_in,
                              void* d_out, int out_size)
{
    const int*   x      = (const int*)d_in[0];
    const int*   w      = (const int*)d_in[1];
    const float* absmax = (const float*)d_in[2];
    const float* code   = (const float*)d_in[3];
    const float* lnw    = (const float*)d_in[4];
    const float* lnb    = (const float*)d_in[5];
    float*       out    = (float*)d_out;

    const int n_tokens = in_sizes[0];   // 16384
    emb_ln_kernel<<<n_tokens, TPB>>>(x, w, absmax, code, lnw, lnb, out);
}

// round 3
// speedup vs baseline: 1.1405x; 1.1405x over previous
#include <cuda_runtime.h>
#include <cuda_bf16.h>

// FrozenBNBStableEmbedding: gather int8-coded rows, dequant via 256-entry
// code table * per-block absmax, LayerNorm with affine.
// R3: 16 tokens per CTA to amortize LN param reads; prefetch next row;
// single barrier per token; streaming stores.

#define D    1024
#define TPB  256
#define TOK  16          // tokens per CTA
#define EPS  1e-5f

__global__ __launch_bounds__(TPB) void emb_ln_kernel(
    const int*   __restrict__ x,
    const int*   __restrict__ w,
    const float* __restrict__ absmax,
    const float* __restrict__ code,
    const float* __restrict__ lnw,
    const float* __restrict__ lnb,
    float*       __restrict__ out,
    int n_tokens)
{
    __shared__ float s_code[256];
    __shared__ int   s_rows[TOK];
    __shared__ float s_part[2][2][8];   // [buf][sum|sq][warp]

    const int tid  = threadIdx.x;
    const int warp = tid >> 5;
    const int lane = tid & 31;
    const int base = blockIdx.x * TOK;

    s_code[tid] = code[tid];
    if (tid < TOK) {
        int idx = base + tid;
        s_rows[tid] = (idx < n_tokens) ? x[idx] : 0;
    }

    // LN params live in registers for all TOK tokens
    const float4 gw = __ldg(&reinterpret_cast<const float4*>(lnw)[tid]);
    const float4 gb = __ldg(&reinterpret_cast<const float4*>(lnb)[tid]);
    __syncthreads();

    // Prime the pipeline: token 0
    int   row   = s_rows[0];
    int4  q     = __ldg(&reinterpret_cast<const int4*>(w + (long long)row * D)[tid]);
    float scale = __ldg(&absmax[row >> 2]);

    const int ntok = min(TOK, n_tokens - base);

    for (int t = 0; t < ntok; ++t) {
        // Prefetch token t+1 while we crunch token t
        int4  qn;
        float scn = 0.0f;
        if (t + 1 < ntok) {
            int rn = s_rows[t + 1];
            qn  = __ldg(&reinterpret_cast<const int4*>(w + (long long)rn * D)[tid]);
            scn = __ldg(&absmax[rn >> 2]);
        }

        float v0 = s_code[q.x & 255] * scale;
        float v1 = s_code[q.y & 255] * scale;
        float v2 = s_code[q.z & 255] * scale;
        float v3 = s_code[q.w & 255] * scale;

        float sum = v0 + v1 + v2 + v3;
        float sq  = v0*v0 + v1*v1 + v2*v2 + v3*v3;

        #pragma unroll
        for (int off = 16; off > 0; off >>= 1) {
            sum += __shfl_xor_sync(0xFFFFFFFFu, sum, off);
            sq  += __shfl_xor_sync(0xFFFFFFFFu, sq,  off);
        }
        const int buf = t & 1;
        if (lane == 0) { s_part[buf][0][warp] = sum; s_part[buf][1][warp] = sq; }
        __syncthreads();

        // Every warp reduces the 8 partials redundantly -> no second barrier
        float s = (lane < 8) ? s_part[buf][0][lane] : 0.0f;
        float z = (lane < 8) ? s_part[buf][1][lane] : 0.0f;
        #pragma unroll
        for (int off = 4; off > 0; off >>= 1) {
            s += __shfl_xor_sync(0xFFFFFFFFu, s, off);
            z += __shfl_xor_sync(0xFFFFFFFFu, z, off);
        }
        const float mean = __shfl_sync(0xFFFFFFFFu, s, 0) * (1.0f / D);
        const float msq  = __shfl_sync(0xFFFFFFFFu, z, 0) * (1.0f / D);
        const float rstd = rsqrtf(msq - mean * mean + EPS);

        float4 o;
        o.x = (v0 - mean) * rstd * gw.x + gb.x;
        o.y = (v1 - mean) * rstd * gw.y + gb.y;
        o.z = (v2 - mean) * rstd * gw.z + gb.z;
        o.w = (v3 - mean) * rstd * gw.w + gb.w;

        // Streaming store: keep L2 capacity for weight rows
        __stcs(&reinterpret_cast<float4*>(out)[(long long)(base + t) * (D / 4) + tid], o);

        q     = qn;
        scale = scn;
    }
}

extern "C" void kernel_launch(void* const* d_in, const int* in_sizes, int n_in,
                              void* d_out, int out_size)
{
    const int*   x      = (const int*)d_in[0];
    const int*   w      = (const int*)d_in[1];
    const float* absmax = (const float*)d_in[2];
    const float* code   = (const float*)d_in[3];
    const float* lnw    = (const float*)d_in[4];
    const float* lnb    = (const float*)d_in[5];
    float*       out    = (float*)d_out;

    const int n_tokens = in_sizes[0];                 // 16384
    const int grid = (n_tokens + TOK - 1) / TOK;      // 1024
    emb_ln_kernel<<<grid, TPB>>>(x, w, absmax, code, lnw, lnb, out, n_tokens);
}